// round 16
// baseline (speedup 1.0000x reference)
#include <cuda_runtime.h>
#include <math.h>

#define N_NODES 100000
#define D_IN    64
#define D_H     32
#define TOTAL_H (N_NODES * D_H)
#define PBM     64                                   // prep nodes per block
#define PXS     68                                   // padded sX stride
#define PREP_BLOCKS ((N_NODES + PBM - 1) / PBM)      // 1563
#define ZB      296                                  // zero blocks in K1
#define SCB     888                                  // scatter blocks in K2 (1-in-2)

// ---------------- scratch (device globals, 16B aligned) ---------------------
__device__ __align__(16) float g_aggp[TOTAL_H];
__device__ __align__(16) float g_aggc[TOTAL_H];
__device__ __align__(16) float g_ycp [TOTAL_H];
__device__ __align__(16) float g_ypc [TOTAL_H];
__device__ __align__(16) float g_linc[TOTAL_H];
__device__ __align__(16) float g_linp[TOTAL_H];
__device__ __align__(16) float g_cntp[N_NODES];
__device__ __align__(16) float g_cntc[N_NODES];
__device__ __align__(16) float g_gc  [N_NODES];
__device__ __align__(16) float g_aggs[N_NODES];
__device__ float g_w2l_eff[D_H];
__device__ float g_w2r_eff[D_H];
__device__ float g_bias_eff[1];

// ---------------- dual prep body (proven): y = x@Wl, lin = x@Wr + b ----------
__device__ __forceinline__ void prep_body(int pbid, const float* __restrict__ x,
        const float* __restrict__ Wl, const float* __restrict__ Wr,
        const float* __restrict__ b,
        float* __restrict__ y, float* __restrict__ lin, int n,
        float* sW, float* sX, float* sb2) {
    int tid = threadIdx.x;
    for (int i = tid; i < D_IN * 8; i += 128) {
        int k = i >> 3, q = i & 7;
        reinterpret_cast<float4*>(sW)[k * 16 + q]     = reinterpret_cast<const float4*>(Wl)[i];
        reinterpret_cast<float4*>(sW)[k * 16 + 8 + q] = reinterpret_cast<const float4*>(Wr)[i];
    }
    if (tid < D_H) sb2[tid] = b[tid];

    int base = pbid * PBM;
    for (int i = tid; i < PBM * 16; i += 128) {
        int node = i >> 4;
        int q    = i & 15;
        int gn = base + node;
        float4 v = (gn < n) ? reinterpret_cast<const float4*>(x + (size_t)gn * D_IN)[q]
                            : make_float4(0.f, 0.f, 0.f, 0.f);
        int k4 = q * 4;
        sX[(k4 + 0) * PXS + node] = v.x;
        sX[(k4 + 1) * PXS + node] = v.y;
        sX[(k4 + 2) * PXS + node] = v.z;
        sX[(k4 + 3) * PXS + node] = v.w;
    }
    __syncthreads();

    int tn = tid & 15;
    int tm = tid >> 4;
    int n0 = tn * 4, m0 = tm * 8;

    float acc[8][4];
    #pragma unroll
    for (int i = 0; i < 8; ++i)
        #pragma unroll
        for (int j = 0; j < 4; ++j) acc[i][j] = 0.f;

    #pragma unroll 4
    for (int k = 0; k < D_IN; ++k) {
        float4 w  = *reinterpret_cast<const float4*>(&sW[k * 64 + n0]);
        float4 xa = *reinterpret_cast<const float4*>(&sX[k * PXS + m0]);
        float4 xb = *reinterpret_cast<const float4*>(&sX[k * PXS + m0 + 4]);
        float xm[8] = {xa.x, xa.y, xa.z, xa.w, xb.x, xb.y, xb.z, xb.w};
        #pragma unroll
        for (int i = 0; i < 8; ++i) {
            acc[i][0] += xm[i] * w.x;
            acc[i][1] += xm[i] * w.y;
            acc[i][2] += xm[i] * w.z;
            acc[i][3] += xm[i] * w.w;
        }
    }

    bool isLin = (tn >= 8);
    int col = isLin ? (n0 - 32) : n0;
    float4 bw = isLin ? *reinterpret_cast<const float4*>(&sb2[col])
                      : make_float4(0.f, 0.f, 0.f, 0.f);
    float* dst = isLin ? lin : y;
    #pragma unroll
    for (int i = 0; i < 8; ++i) {
        int gn = base + m0 + i;
        if (gn < n) {
            float4 v = make_float4(acc[i][0] + bw.x, acc[i][1] + bw.y,
                                   acc[i][2] + bw.z, acc[i][3] + bw.w);
            *reinterpret_cast<float4*>(dst + (size_t)gn * D_H + col) = v;
        }
    }
}

// ---------------- single prep body: out = x@W (+b if BIAS). Half the FFMA. ---
template<bool BIAS>
__device__ __forceinline__ void prep_single(int pbid, const float* __restrict__ x,
        const float* __restrict__ W, const float* __restrict__ b,
        float* __restrict__ out, int n,
        float* sW, float* sX, float* sb2) {
    int tid = threadIdx.x;
    for (int i = tid; i < D_IN * 8; i += 128)
        reinterpret_cast<float4*>(sW)[i] = reinterpret_cast<const float4*>(W)[i];
    if (BIAS && tid < D_H) sb2[tid] = b[tid];

    int base = pbid * PBM;
    for (int i = tid; i < PBM * 16; i += 128) {
        int node = i >> 4;
        int q    = i & 15;
        int gn = base + node;
        float4 v = (gn < n) ? reinterpret_cast<const float4*>(x + (size_t)gn * D_IN)[q]
                            : make_float4(0.f, 0.f, 0.f, 0.f);
        int k4 = q * 4;
        sX[(k4 + 0) * PXS + node] = v.x;
        sX[(k4 + 1) * PXS + node] = v.y;
        sX[(k4 + 2) * PXS + node] = v.z;
        sX[(k4 + 3) * PXS + node] = v.w;
    }
    __syncthreads();

    int tn = tid & 7;        // 8 col groups x 4 cols = 32 cols
    int tm = tid >> 3;       // 16 node groups x 4 nodes = 64 nodes
    int n0 = tn * 4, m0 = tm * 4;

    float acc[4][4];
    #pragma unroll
    for (int i = 0; i < 4; ++i)
        #pragma unroll
        for (int j = 0; j < 4; ++j) acc[i][j] = 0.f;

    #pragma unroll 4
    for (int k = 0; k < D_IN; ++k) {
        float4 w  = *reinterpret_cast<const float4*>(&sW[k * 32 + n0]);
        float4 xa = *reinterpret_cast<const float4*>(&sX[k * PXS + m0]);
        float xm[4] = {xa.x, xa.y, xa.z, xa.w};
        #pragma unroll
        for (int i = 0; i < 4; ++i) {
            acc[i][0] += xm[i] * w.x;
            acc[i][1] += xm[i] * w.y;
            acc[i][2] += xm[i] * w.z;
            acc[i][3] += xm[i] * w.w;
        }
    }

    float4 bw = BIAS ? *reinterpret_cast<const float4*>(&sb2[n0])
                     : make_float4(0.f, 0.f, 0.f, 0.f);
    #pragma unroll
    for (int i = 0; i < 4; ++i) {
        int gn = base + m0 + i;
        if (gn < n) {
            float4 v = make_float4(acc[i][0] + bw.x, acc[i][1] + bw.y,
                                   acc[i][2] + bw.z, acc[i][3] + bw.w);
            *reinterpret_cast<float4*>(out + (size_t)gn * D_H + n0) = v;
        }
    }
}

// ---------------- K1: zero + eff  ||  y_pc (single, no bias) -----------------
__global__ void k1_zero_prep(const float* __restrict__ xp,
                             const float* __restrict__ W1l_r2,
                             const float* __restrict__ W2l, const float* __restrict__ W2r,
                             const float* __restrict__ b2, const float* __restrict__ Wlin,
                             const float* __restrict__ blin, int n) {
    __shared__ float sW[D_IN * 64];
    __shared__ float sX[D_IN * PXS];
    __shared__ float sb2[D_H];
    int bid = blockIdx.x;
    if (bid < ZB) {
        if (bid == 0 && threadIdx.x < 32) {
            int i = threadIdx.x;
            float wl = 0.f, wr = 0.f;
            #pragma unroll
            for (int j = 0; j < D_H; ++j) {
                float wj = Wlin[j];
                wl += W2l[i * D_H + j] * wj;
                wr += W2r[i * D_H + j] * wj;
            }
            g_w2l_eff[i] = wl;
            g_w2r_eff[i] = wr;
            float bv = b2[i] * Wlin[i];
            #pragma unroll
            for (int o = 16; o; o >>= 1) bv += __shfl_xor_sync(0xffffffffu, bv, o);
            if (i == 0) g_bias_eff[0] = bv + blin[0];
        }
        int i = bid * 128 + threadIdx.x;
        int stride = ZB * 128;
        float4 z = make_float4(0.f, 0.f, 0.f, 0.f);
        for (int k = i; k < TOTAL_H / 4; k += stride) {
            reinterpret_cast<float4*>(g_aggp)[k] = z;
            reinterpret_cast<float4*>(g_aggc)[k] = z;
        }
        for (int k = i; k < N_NODES / 4; k += stride) {
            reinterpret_cast<float4*>(g_cntp)[k] = z;
            reinterpret_cast<float4*>(g_cntc)[k] = z;
            reinterpret_cast<float4*>(g_aggs)[k] = z;
        }
    } else {
        prep_single<false>(bid - ZB, xp, W1l_r2, nullptr, g_ypc, n, sW, sX, sb2);
    }
}

// ---------------- K2: p2c scatter (1-in-2)  ||  prep_c dual + lin_p single ---
__global__ void k2_scat_prep(const int* __restrict__ edge, int E,
                             const float* __restrict__ xc,
                             const float* __restrict__ W1l_r1, const float* __restrict__ W1r_r2,
                             const float* __restrict__ b1_r2,
                             const float* __restrict__ xp,
                             const float* __restrict__ W1r_r1, const float* __restrict__ b1_r1,
                             int n) {
    __shared__ float sW[D_IN * 64];
    __shared__ float sX[D_IN * PXS];
    __shared__ float sb2[D_H];
    int bid = blockIdx.x;
    bool isScat = (bid < 2 * SCB) && ((bid & 1) == 0);
    if (isScat) {
        int sb = bid >> 1;
        long long lanes  = (long long)E * 8;
        long long stride = (long long)SCB * 128;
        long long t = (long long)sb * 128 + threadIdx.x;
        for (; t + stride < lanes; t += 2 * stride) {
            long long t2 = t + stride;
            int e0 = (int)(t >> 3),  l0 = (int)(t & 7);
            int e1 = (int)(t2 >> 3), l1 = (int)(t2 & 7);
            int s0 = __ldg(&edge[e0]), d0 = __ldg(&edge[E + e0]);
            int s1 = __ldg(&edge[e1]), d1 = __ldg(&edge[E + e1]);
            float4 v0 = *reinterpret_cast<const float4*>(g_ypc + (size_t)s0 * D_H + l0 * 4);
            float4 v1 = *reinterpret_cast<const float4*>(g_ypc + (size_t)s1 * D_H + l1 * 4);
            atomicAdd(reinterpret_cast<float4*>(g_aggc + (size_t)d0 * D_H + l0 * 4), v0);
            atomicAdd(reinterpret_cast<float4*>(g_aggc + (size_t)d1 * D_H + l1 * 4), v1);
            if (l0 == 0) atomicAdd(g_cntc + d0, 1.0f);
            if (l1 == 0) atomicAdd(g_cntc + d1, 1.0f);
        }
        for (; t < lanes; t += stride) {
            int e = (int)(t >> 3), lane = (int)(t & 7);
            int s = __ldg(&edge[e]), d = __ldg(&edge[E + e]);
            float4 v = *reinterpret_cast<const float4*>(g_ypc + (size_t)s * D_H + lane * 4);
            atomicAdd(reinterpret_cast<float4*>(g_aggc + (size_t)d * D_H + lane * 4), v);
            if (lane == 0) atomicAdd(g_cntc + d, 1.0f);
        }
    } else {
        int pid = (bid < 2 * SCB) ? (bid >> 1)
                                  : (SCB + (bid - 2 * SCB));
        if (pid < PREP_BLOCKS) {
            // customer dual prep: y_cp + lin_c
            prep_body(pid, xc, W1l_r1, W1r_r2, b1_r2, g_ycp, g_linc, n, sW, sX, sb2);
        } else if (pid < 2 * PREP_BLOCKS) {
            // deferred product lin: lin_p = x_p @ W1r_r1 + b1_r1
            prep_single<true>(pid - PREP_BLOCKS, xp, W1r_r1, b1_r1, g_linp, n, sW, sX, sb2);
        }
    }
}

// ---------------- K3: customer post -> g_c -----------------------------------
__global__ void k_post_c(int n) {
    int j = threadIdx.x & 31;
    int warpId = (blockIdx.x * blockDim.x + threadIdx.x) >> 5;
    int nWarps = (gridDim.x * blockDim.x) >> 5;
    float wj = g_w2l_eff[j];
    for (int node = warpId; node < n; node += nWarps) {
        float inv = 1.0f / fmaxf(g_cntc[node], 1.0f);
        float h = fmaxf(g_aggc[(size_t)node * D_H + j] * inv + g_linc[(size_t)node * D_H + j], 0.f);
        float v = h * wj;
        #pragma unroll
        for (int o = 16; o; o >>= 1) v += __shfl_xor_sync(0xffffffffu, v, o);
        if (j == 0) g_gc[node] = v;
    }
}

// ---------------- K4: c2p scatter fused with layer-2 scalar scatter ----------
__global__ void k_scatter32_fused(const int* __restrict__ edge, int E) {
    long long t = (long long)blockIdx.x * blockDim.x + threadIdx.x;
    int e    = (int)(t >> 3);
    int lane = (int)(t & 7);
    if (e >= E) return;
    int s = __ldg(&edge[e]);
    int d = __ldg(&edge[E + e]);
    float4 v = *reinterpret_cast<const float4*>(g_ycp + (size_t)s * D_H + lane * 4);
    atomicAdd(reinterpret_cast<float4*>(g_aggp + (size_t)d * D_H + lane * 4), v);
    if (lane == 0) atomicAdd(g_cntp + d, 1.0f);
    if (lane == 1) atomicAdd(g_aggs + d, __ldg(g_gc + s));
}

// ---------------- K5: product post + head + sigmoid --------------------------
__global__ void k_post_p(float* __restrict__ out, int n) {
    int j = threadIdx.x & 31;
    int warpId = (blockIdx.x * blockDim.x + threadIdx.x) >> 5;
    int nWarps = (gridDim.x * blockDim.x) >> 5;
    float wj = g_w2r_eff[j];
    float beff = g_bias_eff[0];
    for (int node = warpId; node < n; node += nWarps) {
        float inv = 1.0f / fmaxf(g_cntp[node], 1.0f);
        float h = fmaxf(g_aggp[(size_t)node * D_H + j] * inv + g_linp[(size_t)node * D_H + j], 0.f);
        float v = h * wj;
        #pragma unroll
        for (int o = 16; o; o >>= 1) v += __shfl_xor_sync(0xffffffffu, v, o);
        if (j == 0) {
            float logit = g_aggs[node] * inv + v + beff;
            out[node] = 1.0f / (1.0f + expf(-logit));
        }
    }
}

// ---------------- launch ------------------------------------------------------

extern "C" void kernel_launch(void* const* d_in, const int* in_sizes, int n_in,
                              void* d_out, int out_size) {
    const float* x_customer = (const float*)d_in[0];
    const float* x_product  = (const float*)d_in[1];
    const int*   edge_c2p   = (const int*)d_in[2];
    const int*   edge_p2c   = (const int*)d_in[3];
    const float* W1l_r1 = (const float*)d_in[4];
    const float* b1_r1  = (const float*)d_in[5];
    const float* W1r_r1 = (const float*)d_in[6];
    const float* W1l_r2 = (const float*)d_in[7];
    const float* b1_r2  = (const float*)d_in[8];
    const float* W1r_r2 = (const float*)d_in[9];
    const float* W2l_r1 = (const float*)d_in[10];
    const float* b2_r1  = (const float*)d_in[11];
    const float* W2r_r1 = (const float*)d_in[12];
    const float* Wlin   = (const float*)d_in[16];
    const float* blin   = (const float*)d_in[17];
    float* out = (float*)d_out;

    const int N = N_NODES;
    const int E = in_sizes[2] / 2;

    const int TB = 256;
    const int GS_BLOCKS = 1480;

    // K1: zero+eff || y_pc (single prep, half FFMA)
    k1_zero_prep<<<ZB + PREP_BLOCKS, 128>>>(x_product, W1l_r2,
                                            W2l_r1, W2r_r1, b2_r1, Wlin, blin, N);
    // K2: p2c scatter (1-in-2) || prep_c dual + deferred lin_p single
    int workBlocks = 2 * PREP_BLOCKS;
    int k2grid = SCB + workBlocks;          // SCB scatter + workBlocks prep, interleaved
    k2_scat_prep<<<k2grid, 128>>>(edge_p2c, E,
                                  x_customer, W1l_r1, W1r_r2, b1_r2,
                                  x_product, W1r_r1, b1_r1, N);
    // K3: customer post -> g_c
    k_post_c<<<GS_BLOCKS, TB>>>(N);
    // K4: c2p scatter fused with layer-2 scalar scatter
    long long scatThreads = (long long)E * 8;
    int scatBlocks = (int)((scatThreads + TB - 1) / TB);
    k_scatter32_fused<<<scatBlocks, TB>>>(edge_c2p, E);
    // K5: product post + head + sigmoid
    k_post_p<<<GS_BLOCKS, TB>>>(out, N);
}

// round 17
// speedup vs baseline: 1.0128x; 1.0128x over previous
#include <cuda_runtime.h>
#include <math.h>

#define N_NODES 100000
#define D_IN    64
#define D_H     32
#define TOTAL_H (N_NODES * D_H)
#define BM      128                                  // prep nodes per 256-thr block
#define XS      132                                  // padded sX stride
#define PREP_BLOCKS ((N_NODES + BM - 1) / BM)        // 782
#define ZB      296                                  // zero blocks in K1
#define SCB     1564                                 // scatter blocks in K2 (1-in-2)

// ---------------- scratch (device globals, 16B aligned) ---------------------
__device__ __align__(16) float g_aggp[TOTAL_H];
__device__ __align__(16) float g_aggc[TOTAL_H];
__device__ __align__(16) float g_ycp [TOTAL_H];
__device__ __align__(16) float g_ypc [TOTAL_H];
__device__ __align__(16) float g_linc[TOTAL_H];
__device__ __align__(16) float g_linp[TOTAL_H];
__device__ __align__(16) float g_cntp[N_NODES];
__device__ __align__(16) float g_cntc[N_NODES];
__device__ __align__(16) float g_gc  [N_NODES];
__device__ __align__(16) float g_aggs[N_NODES];
__device__ float g_w2l_eff[D_H];
__device__ float g_w2r_eff[D_H];
__device__ float g_bias_eff[1];

// ---------------- dual prep body (proven R9, 256 thr, BM=128) ----------------
__device__ __forceinline__ void prep_dual(int pbid, const float* __restrict__ x,
        const float* __restrict__ Wl, const float* __restrict__ Wr,
        const float* __restrict__ b,
        float* __restrict__ y, float* __restrict__ lin, int n,
        float* sW, float* sX, float* sb2) {
    int tid = threadIdx.x;
    for (int i = tid; i < D_IN * 8; i += 256) {
        int k = i >> 3, q = i & 7;
        reinterpret_cast<float4*>(sW)[k * 16 + q]     = reinterpret_cast<const float4*>(Wl)[i];
        reinterpret_cast<float4*>(sW)[k * 16 + 8 + q] = reinterpret_cast<const float4*>(Wr)[i];
    }
    if (tid < D_H) sb2[tid] = b[tid];

    int base = pbid * BM;
    for (int i = tid; i < BM * 16; i += 256) {
        int node = i >> 4;
        int q    = i & 15;
        int gn = base + node;
        float4 v = (gn < n) ? reinterpret_cast<const float4*>(x + (size_t)gn * D_IN)[q]
                            : make_float4(0.f, 0.f, 0.f, 0.f);
        int k4 = q * 4;
        sX[(k4 + 0) * XS + node] = v.x;
        sX[(k4 + 1) * XS + node] = v.y;
        sX[(k4 + 2) * XS + node] = v.z;
        sX[(k4 + 3) * XS + node] = v.w;
    }
    __syncthreads();

    int tn = tid & 15;
    int tm = tid >> 4;
    int n0 = tn * 4, m0 = tm * 8;

    float acc[8][4];
    #pragma unroll
    for (int i = 0; i < 8; ++i)
        #pragma unroll
        for (int j = 0; j < 4; ++j) acc[i][j] = 0.f;

    #pragma unroll 4
    for (int k = 0; k < D_IN; ++k) {
        float4 w  = *reinterpret_cast<const float4*>(&sW[k * 64 + n0]);
        float4 xa = *reinterpret_cast<const float4*>(&sX[k * XS + m0]);
        float4 xb = *reinterpret_cast<const float4*>(&sX[k * XS + m0 + 4]);
        float xm[8] = {xa.x, xa.y, xa.z, xa.w, xb.x, xb.y, xb.z, xb.w};
        #pragma unroll
        for (int i = 0; i < 8; ++i) {
            acc[i][0] += xm[i] * w.x;
            acc[i][1] += xm[i] * w.y;
            acc[i][2] += xm[i] * w.z;
            acc[i][3] += xm[i] * w.w;
        }
    }

    bool isLin = (tn >= 8);
    int col = isLin ? (n0 - 32) : n0;
    float4 bw = isLin ? *reinterpret_cast<const float4*>(&sb2[col])
                      : make_float4(0.f, 0.f, 0.f, 0.f);
    float* dst = isLin ? lin : y;
    #pragma unroll
    for (int i = 0; i < 8; ++i) {
        int gn = base + m0 + i;
        if (gn < n) {
            float4 v = make_float4(acc[i][0] + bw.x, acc[i][1] + bw.y,
                                   acc[i][2] + bw.z, acc[i][3] + bw.w);
            *reinterpret_cast<float4*>(dst + (size_t)gn * D_H + col) = v;
        }
    }
}

// ---------------- single prep body (256 thr, BM=128): out = x@W (+b) ---------
template<bool BIAS>
__device__ __forceinline__ void prep_single(int pbid, const float* __restrict__ x,
        const float* __restrict__ W, const float* __restrict__ b,
        float* __restrict__ out, int n,
        float* sW, float* sX, float* sb2) {
    int tid = threadIdx.x;
    for (int i = tid; i < D_IN * 8; i += 256)
        reinterpret_cast<float4*>(sW)[i] = reinterpret_cast<const float4*>(W)[i];
    if (BIAS && tid < D_H) sb2[tid] = b[tid];

    int base = pbid * BM;
    for (int i = tid; i < BM * 16; i += 256) {
        int node = i >> 4;
        int q    = i & 15;
        int gn = base + node;
        float4 v = (gn < n) ? reinterpret_cast<const float4*>(x + (size_t)gn * D_IN)[q]
                            : make_float4(0.f, 0.f, 0.f, 0.f);
        int k4 = q * 4;
        sX[(k4 + 0) * XS + node] = v.x;
        sX[(k4 + 1) * XS + node] = v.y;
        sX[(k4 + 2) * XS + node] = v.z;
        sX[(k4 + 3) * XS + node] = v.w;
    }
    __syncthreads();

    int tn = tid & 7;        // 8 col groups x 4 = 32 cols
    int tm = tid >> 3;       // 32 node groups x 4 = 128 nodes
    int n0 = tn * 4, m0 = tm * 4;

    float acc[4][4];
    #pragma unroll
    for (int i = 0; i < 4; ++i)
        #pragma unroll
        for (int j = 0; j < 4; ++j) acc[i][j] = 0.f;

    #pragma unroll 4
    for (int k = 0; k < D_IN; ++k) {
        float4 w  = *reinterpret_cast<const float4*>(&sW[k * 32 + n0]);
        float4 xa = *reinterpret_cast<const float4*>(&sX[k * XS + m0]);
        float xm[4] = {xa.x, xa.y, xa.z, xa.w};
        #pragma unroll
        for (int i = 0; i < 4; ++i) {
            acc[i][0] += xm[i] * w.x;
            acc[i][1] += xm[i] * w.y;
            acc[i][2] += xm[i] * w.z;
            acc[i][3] += xm[i] * w.w;
        }
    }

    float4 bw = BIAS ? *reinterpret_cast<const float4*>(&sb2[n0])
                     : make_float4(0.f, 0.f, 0.f, 0.f);
    #pragma unroll
    for (int i = 0; i < 4; ++i) {
        int gn = base + m0 + i;
        if (gn < n) {
            float4 v = make_float4(acc[i][0] + bw.x, acc[i][1] + bw.y,
                                   acc[i][2] + bw.z, acc[i][3] + bw.w);
            *reinterpret_cast<float4*>(out + (size_t)gn * D_H + n0) = v;
        }
    }
}

// ---------------- K1: zero + eff  ||  y_pc (single, no bias) -----------------
__global__ void k1_zero_prep(const float* __restrict__ xp,
                             const float* __restrict__ W1l_r2,
                             const float* __restrict__ W2l, const float* __restrict__ W2r,
                             const float* __restrict__ b2, const float* __restrict__ Wlin,
                             const float* __restrict__ blin, int n) {
    __shared__ float sW[D_IN * 64];
    __shared__ float sX[D_IN * XS];
    __shared__ float sb2[D_H];
    int bid = blockIdx.x;
    if (bid < ZB) {
        if (bid == 0 && threadIdx.x < 32) {
            int i = threadIdx.x;
            float wl = 0.f, wr = 0.f;
            #pragma unroll
            for (int j = 0; j < D_H; ++j) {
                float wj = Wlin[j];
                wl += W2l[i * D_H + j] * wj;
                wr += W2r[i * D_H + j] * wj;
            }
            g_w2l_eff[i] = wl;
            g_w2r_eff[i] = wr;
            float bv = b2[i] * Wlin[i];
            #pragma unroll
            for (int o = 16; o; o >>= 1) bv += __shfl_xor_sync(0xffffffffu, bv, o);
            if (i == 0) g_bias_eff[0] = bv + blin[0];
        }
        int i = bid * 256 + threadIdx.x;
        int stride = ZB * 256;
        float4 z = make_float4(0.f, 0.f, 0.f, 0.f);
        for (int k = i; k < TOTAL_H / 4; k += stride) {
            reinterpret_cast<float4*>(g_aggp)[k] = z;
            reinterpret_cast<float4*>(g_aggc)[k] = z;
        }
        for (int k = i; k < N_NODES / 4; k += stride) {
            reinterpret_cast<float4*>(g_cntp)[k] = z;
            reinterpret_cast<float4*>(g_cntc)[k] = z;
            reinterpret_cast<float4*>(g_aggs)[k] = z;
        }
    } else {
        prep_single<false>(bid - ZB, xp, W1l_r2, nullptr, g_ypc, n, sW, sX, sb2);
    }
}

// ---------------- K2: p2c scatter (1-in-2, 256 thr)  ||  prep_c + lin_p ------
__global__ void k2_scat_prep(const int* __restrict__ edge, int E,
                             const float* __restrict__ xc,
                             const float* __restrict__ W1l_r1, const float* __restrict__ W1r_r2,
                             const float* __restrict__ b1_r2,
                             const float* __restrict__ xp,
                             const float* __restrict__ W1r_r1, const float* __restrict__ b1_r1,
                             int n) {
    __shared__ float sW[D_IN * 64];
    __shared__ float sX[D_IN * XS];
    __shared__ float sb2[D_H];
    int bid = blockIdx.x;
    if ((bid & 1) == 0) {   // scatter blocks: even bids, sb in [0, SCB)
        int sb = bid >> 1;
        long long lanes  = (long long)E * 8;
        long long stride = (long long)SCB * 256;
        long long t = (long long)sb * 256 + threadIdx.x;
        for (; t + stride < lanes; t += 2 * stride) {
            long long t2 = t + stride;
            int e0 = (int)(t >> 3),  l0 = (int)(t & 7);
            int e1 = (int)(t2 >> 3), l1 = (int)(t2 & 7);
            int s0 = __ldg(&edge[e0]), d0 = __ldg(&edge[E + e0]);
            int s1 = __ldg(&edge[e1]), d1 = __ldg(&edge[E + e1]);
            float4 v0 = *reinterpret_cast<const float4*>(g_ypc + (size_t)s0 * D_H + l0 * 4);
            float4 v1 = *reinterpret_cast<const float4*>(g_ypc + (size_t)s1 * D_H + l1 * 4);
            atomicAdd(reinterpret_cast<float4*>(g_aggc + (size_t)d0 * D_H + l0 * 4), v0);
            atomicAdd(reinterpret_cast<float4*>(g_aggc + (size_t)d1 * D_H + l1 * 4), v1);
            if (l0 == 0) atomicAdd(g_cntc + d0, 1.0f);
            if (l1 == 0) atomicAdd(g_cntc + d1, 1.0f);
        }
        for (; t < lanes; t += stride) {
            int e = (int)(t >> 3), lane = (int)(t & 7);
            int s = __ldg(&edge[e]), d = __ldg(&edge[E + e]);
            float4 v = *reinterpret_cast<const float4*>(g_ypc + (size_t)s * D_H + lane * 4);
            atomicAdd(reinterpret_cast<float4*>(g_aggc + (size_t)d * D_H + lane * 4), v);
            if (lane == 0) atomicAdd(g_cntc + d, 1.0f);
        }
    } else {
        int pid = bid >> 1;                 // odd bids: pid in [0, SCB)
        if (pid < PREP_BLOCKS) {
            // customer dual prep: y_cp + lin_c
            prep_dual(pid, xc, W1l_r1, W1r_r2, b1_r2, g_ycp, g_linc, n, sW, sX, sb2);
        } else if (pid < 2 * PREP_BLOCKS) {
            // deferred product lin: lin_p = x_p @ W1r_r1 + b1_r1
            prep_single<true>(pid - PREP_BLOCKS, xp, W1r_r1, b1_r1, g_linp, n, sW, sX, sb2);
        }
    }
}

// ---------------- K3: customer post -> g_c -----------------------------------
__global__ void k_post_c(int n) {
    int j = threadIdx.x & 31;
    int warpId = (blockIdx.x * blockDim.x + threadIdx.x) >> 5;
    int nWarps = (gridDim.x * blockDim.x) >> 5;
    float wj = g_w2l_eff[j];
    for (int node = warpId; node < n; node += nWarps) {
        float inv = 1.0f / fmaxf(g_cntc[node], 1.0f);
        float h = fmaxf(g_aggc[(size_t)node * D_H + j] * inv + g_linc[(size_t)node * D_H + j], 0.f);
        float v = h * wj;
        #pragma unroll
        for (int o = 16; o; o >>= 1) v += __shfl_xor_sync(0xffffffffu, v, o);
        if (j == 0) g_gc[node] = v;
    }
}

// ---------------- K4: c2p scatter fused with layer-2 scalar scatter ----------
__global__ void k_scatter32_fused(const int* __restrict__ edge, int E) {
    long long t = (long long)blockIdx.x * blockDim.x + threadIdx.x;
    int e    = (int)(t >> 3);
    int lane = (int)(t & 7);
    if (e >= E) return;
    int s = __ldg(&edge[e]);
    int d = __ldg(&edge[E + e]);
    float4 v = *reinterpret_cast<const float4*>(g_ycp + (size_t)s * D_H + lane * 4);
    atomicAdd(reinterpret_cast<float4*>(g_aggp + (size_t)d * D_H + lane * 4), v);
    if (lane == 0) atomicAdd(g_cntp + d, 1.0f);
    if (lane == 1) atomicAdd(g_aggs + d, __ldg(g_gc + s));
}

// ---------------- K5: product post + head + sigmoid --------------------------
__global__ void k_post_p(float* __restrict__ out, int n) {
    int j = threadIdx.x & 31;
    int warpId = (blockIdx.x * blockDim.x + threadIdx.x) >> 5;
    int nWarps = (gridDim.x * blockDim.x) >> 5;
    float wj = g_w2r_eff[j];
    float beff = g_bias_eff[0];
    for (int node = warpId; node < n; node += nWarps) {
        float inv = 1.0f / fmaxf(g_cntp[node], 1.0f);
        float h = fmaxf(g_aggp[(size_t)node * D_H + j] * inv + g_linp[(size_t)node * D_H + j], 0.f);
        float v = h * wj;
        #pragma unroll
        for (int o = 16; o; o >>= 1) v += __shfl_xor_sync(0xffffffffu, v, o);
        if (j == 0) {
            float logit = g_aggs[node] * inv + v + beff;
            out[node] = 1.0f / (1.0f + expf(-logit));
        }
    }
}

// ---------------- launch ------------------------------------------------------

extern "C" void kernel_launch(void* const* d_in, const int* in_sizes, int n_in,
                              void* d_out, int out_size) {
    const float* x_customer = (const float*)d_in[0];
    const float* x_product  = (const float*)d_in[1];
    const int*   edge_c2p   = (const int*)d_in[2];
    const int*   edge_p2c   = (const int*)d_in[3];
    const float* W1l_r1 = (const float*)d_in[4];
    const float* b1_r1  = (const float*)d_in[5];
    const float* W1r_r1 = (const float*)d_in[6];
    const float* W1l_r2 = (const float*)d_in[7];
    const float* b1_r2  = (const float*)d_in[8];
    const float* W1r_r2 = (const float*)d_in[9];
    const float* W2l_r1 = (const float*)d_in[10];
    const float* b2_r1  = (const float*)d_in[11];
    const float* W2r_r1 = (const float*)d_in[12];
    const float* Wlin   = (const float*)d_in[16];
    const float* blin   = (const float*)d_in[17];
    float* out = (float*)d_out;

    const int N = N_NODES;
    const int E = in_sizes[2] / 2;

    const int TB = 256;
    const int GS_BLOCKS = 1480;

    // K1: zero+eff || y_pc (single prep, BM=128, 256 thr)
    k1_zero_prep<<<ZB + PREP_BLOCKS, 256>>>(x_product, W1l_r2,
                                            W2l_r1, W2r_r1, b2_r1, Wlin, blin, N);
    // K2: p2c scatter (1-in-2, 256 thr) || dual prep_c + deferred lin_p
    k2_scat_prep<<<2 * SCB, 256>>>(edge_p2c, E,
                                   x_customer, W1l_r1, W1r_r2, b1_r2,
                                   x_product, W1r_r1, b1_r1, N);
    // K3: customer post -> g_c
    k_post_c<<<GS_BLOCKS, TB>>>(N);
    // K4: c2p scatter fused with layer-2 scalar scatter
    long long scatThreads = (long long)E * 8;
    int scatBlocks = (int)((scatThreads + TB - 1) / TB);
    k_scatter32_fused<<<scatBlocks, TB>>>(edge_c2p, E);
    // K5: product post + head + sigmoid
    k_post_p<<<GS_BLOCKS, TB>>>(out, N);
}